// round 17
// baseline (speedup 1.0000x reference)
#include <cuda_runtime.h>
#include <math.h>

#define N_FFT   2048
#define HOP     512
#define NT      2880000
#define NFRAMES 5626            // 1 + NT/HOP
#define NPAIRS  2813            // NFRAMES/2
#define PAD     1024            // N_FFT/2
#define NCH     2

#define CHUNK     256
#define WARM      13312
#define NC        11250         // NT / CHUNK (exact)
#define SPAN      512           // samples stored per lane (2 chained chunks)
#define NTILES2   432           // (WARM + SPAN) / 32
#define WARMT2    416           // WARM / 32

#define TWO_PI_F 6.2831853071795864769f
#define LN10_F   2.3025850929940457f

// Scratch (device globals — no allocation allowed)
__device__ float g_sigA[NCH * NT];
__device__ float g_sigB[NCH * NT];
__device__ float g_frames[NCH * NFRAMES * N_FFT];   // reused as gs after OLA4
__device__ float g_win[N_FFT];
__device__ float g_maskT[4][N_FFT];                 // per-band EQ mask by storage bin
__device__ float2 g_twb[128];                       // e^{-2pi i tid/2048}
__device__ float2 g_twb128[8];                      // e^{-2pi i j/128}

struct C2 { float x, y; };
__device__ __forceinline__ C2 cmulC(C2 a, C2 b) { return { a.x*b.x - a.y*b.y, a.x*b.y + a.y*b.x }; }
__device__ __forceinline__ C2 caddC(C2 a, C2 b) { return { a.x + b.x, a.y + b.y }; }
__device__ __forceinline__ C2 csubC(C2 a, C2 b) { return { a.x - b.x, a.y - b.y }; }

__device__ __forceinline__ int SWZ(int p) { return p + (p >> 5); }

// fill hann window + twiddle base tables (accurate path, once per launch)
__global__ void win_init_kernel()
{
    int j = blockIdx.x * blockDim.x + threadIdx.x;
    if (j < N_FFT)
        g_win[j] = 0.5f - 0.5f * cosf((TWO_PI_F / (float)N_FFT) * (float)j);
    if (j < 128) {
        float s, c;
        sincosf(-(TWO_PI_F / (float)N_FFT) * (float)j, &s, &c);
        g_twb[j] = make_float2(c, s);
    }
    if (j < 8) {
        float s, c;
        sincosf(-(TWO_PI_F / 128.f) * (float)j, &s, &c);
        g_twb128[j] = make_float2(c, s);
    }
}

// per-band mask table: mask[k] = 1 + (10^(gdb/20)-1) * exp(-((f(k)-fc)/fc)^2)
__global__ void mask_init_kernel(const float* __restrict__ g0, const float* __restrict__ g1,
                                 const float* __restrict__ g2, const float* __restrict__ g3)
{
    int k = blockIdx.x * blockDim.x + threadIdx.x;
    if (k >= N_FFT) return;
    const float fcs[4] = { 100.f, 500.f, 3000.f, 10000.f };
    float gdb[4] = { g0[0], g1[0], g2[0], g3[0] };
    int ks = min(k, N_FFT - k);
    float fr = (float)ks * (24000.f / 1024.f);
#pragma unroll
    for (int b = 0; b < 4; ++b) {
        float gm1 = exp10f(gdb[b] * 0.05f) - 1.f;
        float rr = (fr - fcs[b]) / fcs[b];
        g_maskT[b][k] = 1.f + gm1 * expf(-rr * rr);
    }
}

template<int SGN>
__device__ __forceinline__ void dft8(C2 v[8]) {
    const float r = 0.70710678118654752f;
    const float S = (float)SGN;
    C2 a0 = caddC(v[0], v[4]), a1 = csubC(v[0], v[4]);
    C2 a2 = caddC(v[2], v[6]), a3 = csubC(v[2], v[6]);
    C2 E0 = caddC(a0, a2), E2 = csubC(a0, a2);
    C2 E1 = { a1.x - S * a3.y, a1.y + S * a3.x };
    C2 E3 = { a1.x + S * a3.y, a1.y - S * a3.x };
    C2 b0 = caddC(v[1], v[5]), b1 = csubC(v[1], v[5]);
    C2 b2 = caddC(v[3], v[7]), b3 = csubC(v[3], v[7]);
    C2 O0 = caddC(b0, b2), O2 = csubC(b0, b2);
    C2 O1 = { b1.x - S * b3.y, b1.y + S * b3.x };
    C2 O3 = { b1.x + S * b3.y, b1.y - S * b3.x };
    C2 T1 = { r * (O1.x - S * O1.y), r * (O1.y + S * O1.x) };
    C2 T2 = { -S * O2.y, S * O2.x };
    C2 T3 = { -r * (O3.x + S * O3.y), r * (S * O3.x - O3.y) };
    v[0] = caddC(E0, O0); v[4] = csubC(E0, O0);
    v[1] = caddC(E1, T1); v[5] = csubC(E1, T1);
    v[2] = caddC(E2, T2); v[6] = csubC(E2, T2);
    v[3] = caddC(E3, T3); v[7] = csubC(E3, T3);
}

// 16-point DFT: two dft8 halves + constant rotations
template<int SGN>
__device__ __forceinline__ void dft16(C2 v[16]) {
    const float S = (float)SGN;
    const float c1 = 0.92387953251128675613f;   // cos(pi/8)
    const float s1 = 0.38268343236508977173f;   // sin(pi/8)
    const float r  = 0.70710678118654752440f;
    C2 e[8], o[8];
#pragma unroll
    for (int i = 0; i < 8; ++i) { e[i] = v[2*i]; o[i] = v[2*i+1]; }
    dft8<SGN>(e);
    dft8<SGN>(o);
    o[1] = cmulC(o[1], C2{ c1, S*s1});
    o[2] = cmulC(o[2], C2{ r,  S*r });
    o[3] = cmulC(o[3], C2{ s1, S*c1});
    o[4] = C2{ -S*o[4].y, S*o[4].x };
    o[5] = cmulC(o[5], C2{-s1, S*c1});
    o[6] = cmulC(o[6], C2{-r,  S*r });
    o[7] = cmulC(o[7], C2{-c1, S*s1});
#pragma unroll
    for (int k = 0; k < 8; ++k) { v[k] = caddC(e[k], o[k]); v[k+8] = csubC(e[k], o[k]); }
}

// twiddle powers W[1..15] of w1 via a depth-4 product tree
__device__ __forceinline__ void twiddle_pows(C2 w1, C2 W[16]) {
    W[1] = w1;
    W[2] = cmulC(w1, w1);
    W[4] = cmulC(W[2], W[2]);
    W[8] = cmulC(W[4], W[4]);
    W[3] = cmulC(W[2], w1);
    W[5] = cmulC(W[4], w1);
    W[6] = cmulC(W[4], W[2]);
    W[7] = cmulC(W[4], W[3]);
    W[9]  = cmulC(W[8], w1);
    W[10] = cmulC(W[8], W[2]);
    W[11] = cmulC(W[8], W[3]);
    W[12] = cmulC(W[8], W[4]);
    W[13] = cmulC(W[8], W[5]);
    W[14] = cmulC(W[8], W[6]);
    W[15] = cmulC(W[8], W[7]);
}

// one radix-16 exchange stage (smem -> smem); base twiddle w1f is the FORWARD
// value (table); inverse stages conjugate it (powers of conj = conj of powers).
template<int SGN>
__device__ __forceinline__ void stage16(float2* sh, int M, int j, int base, float2 w1f) {
    const int span = M >> 4;
    const int p0 = base + j;
    C2 v[16];
#pragma unroll
    for (int k = 0; k < 16; ++k) {
        float2 t = sh[SWZ(p0 + k * span)];
        v[k] = { t.x, t.y };
    }
    C2 w1 = { w1f.x, (SGN < 0) ? w1f.y : -w1f.y };
    C2 W[16];
    twiddle_pows(w1, W);
    if (SGN < 0) {
        dft16<-1>(v);
#pragma unroll
        for (int k = 1; k < 16; ++k) v[k] = cmulC(v[k], W[k]);
    } else {
#pragma unroll
        for (int k = 1; k < 16; ++k) v[k] = cmulC(v[k], W[k]);
        dft16<1>(v);
    }
#pragma unroll
    for (int k = 0; k < 16; ++k)
        sh[SWZ(p0 + k * span)] = make_float2(v[k].x, v[k].y);
}

// One block = one (channel, frame-pair). Two real frames packed into one complex FFT.
// 2048 = 16 x 16 x 8; first/last radix-16 stages fused with gmem load/store.
// All transcendentals replaced by L1-cached tables (mask + twiddle bases) — the
// MUFU pipe (16 expf + 8 sincos-MUFU per thread) was a hidden serial bottleneck.
// storage p = d1*128 + d2*8 + i  <->  frequency k = d1 + 16*d2 + 256*i
__global__ void __launch_bounds__(128)
eq_pair_kernel(const float* __restrict__ x, float* __restrict__ frames, int band)
{
    __shared__ float2 sh[N_FFT + (N_FFT >> 5)];

    const int tid = threadIdx.x;
    const int P = blockIdx.x;
    const int c = blockIdx.y;
    const int f0 = 2 * P;

    const float* xc = x + c * NT;
    const float2 wb = g_twb[tid];

    // ---- fused: windowed reflect-pad load + first forward radix-16 stage
    {
        C2 v[16];
#pragma unroll
        for (int k = 0; k < 16; ++k) {
            int j = tid + 128 * k;
            float w = g_win[j];
            int s0 = f0 * HOP + j - PAD;
            if (s0 < 0) s0 = -s0;
            if (s0 >= NT) s0 = 2 * NT - 2 - s0;
            int s1 = (f0 + 1) * HOP + j - PAD;
            if (s1 < 0) s1 = -s1;
            if (s1 >= NT) s1 = 2 * NT - 2 - s1;
            v[k] = { xc[s0] * w, xc[s1] * w };
        }
        C2 W[16];
        twiddle_pows(C2{ wb.x, wb.y }, W);
        dft16<-1>(v);
#pragma unroll
        for (int k = 1; k < 16; ++k) v[k] = cmulC(v[k], W[k]);
#pragma unroll
        for (int k = 0; k < 16; ++k)
            sh[SWZ(tid + k * 128)] = make_float2(v[k].x, v[k].y);
    }
    __syncthreads();

    stage16<-1>(sh, 128, tid & 7, (tid >> 3) << 7, g_twb128[tid & 7]);
    __syncthreads();

    // fused: forward radix-8 + table mask + inverse radix-8 (2 groups/thread)
    {
        const float* mk = g_maskT[band];
#pragma unroll
        for (int h = 0; h < 2; ++h) {
            int base = tid * 16 + h * 8;
            C2 u[8];
#pragma unroll
            for (int i = 0; i < 8; ++i) {
                float2 t = sh[SWZ(base + i)];
                u[i] = { t.x, t.y };
            }
            dft8<-1>(u);
            int d1 = (base >> 7) & 15, d2 = (base >> 3) & 15;
            int kbase = d1 + (d2 << 4);
#pragma unroll
            for (int i = 0; i < 8; ++i) {
                float fac = mk[kbase + (i << 8)];
                u[i].x *= fac; u[i].y *= fac;
            }
            dft8<1>(u);
#pragma unroll
            for (int i = 0; i < 8; ++i)
                sh[SWZ(base + i)] = make_float2(u[i].x, u[i].y);
        }
    }
    __syncthreads();

    stage16<1>(sh, 128, tid & 7, (tid >> 3) << 7, g_twb128[tid & 7]);
    __syncthreads();

    // ---- fused: last inverse radix-16 stage + windowed store to gmem
    {
        C2 v[16];
#pragma unroll
        for (int k = 0; k < 16; ++k) {
            float2 t = sh[SWZ(tid + k * 128)];
            v[k] = { t.x, t.y };
        }
        C2 W[16];
        twiddle_pows(C2{ wb.x, -wb.y }, W);
#pragma unroll
        for (int k = 1; k < 16; ++k) v[k] = cmulC(v[k], W[k]);
        dft16<1>(v);
        float* fo0 = frames + (c * NFRAMES + f0) * N_FFT;
        float* fo1 = fo0 + N_FFT;
#pragma unroll
        for (int k = 0; k < 16; ++k) {
            int j = tid + 128 * k;
            float s = g_win[j] * (1.f / (float)N_FFT);
            fo0[j] = v[k].x * s;
            fo1[j] = v[k].y * s;
        }
    }
}

// OLA. Interior (all 4 frames present): wsum == 1.5 exactly (Hann^2, 4x overlap).
__device__ __forceinline__ float ola_at(const float* __restrict__ frames, int c, int t)
{
    int tt = t + PAD;
    int fhi = tt >> 9;
    if (tt >= (N_FFT - HOP) && fhi <= NFRAMES - 1) {
        const float* base = frames + c * NFRAMES * N_FFT;
        int f = fhi - 3;
        int n = tt - f * HOP;   // in [1536, 2048)
        float s = base[f * N_FFT + n]
                + base[(f + 1) * N_FFT + (n - HOP)]
                + base[(f + 2) * N_FFT + (n - 2 * HOP)]
                + base[(f + 3) * N_FFT + (n - 3 * HOP)];
        return s * (2.f / 3.f);
    }
    int fmax = fhi;                                    if (fmax > NFRAMES - 1) fmax = NFRAMES - 1;
    int fmin = (tt - (N_FFT - 1) + (HOP - 1)) / HOP;   if (fmin < 0) fmin = 0;
    float sum = 0.f, ws = 0.f;
    for (int f = fmin; f <= fmax; ++f) {
        int n = tt - f * HOP;
        sum += frames[(c * NFRAMES + f) * N_FFT + n];
        float w = g_win[n];
        ws += w * w;
    }
    return sum / (ws > 1e-11f ? ws : 1.f);
}

__global__ void ola_kernel(const float* __restrict__ frames, float* __restrict__ out)
{
    int idx = blockIdx.x * blockDim.x + threadIdx.x;
    if (idx >= NCH * NT) return;
    int c = idx / NT;
    int t = idx - c * NT;
    out[idx] = ola_at(frames, c, t);
}

// final OLA fused with gain-reduction computation
__global__ void ola_gr_kernel(const float* __restrict__ frames, float* __restrict__ out,
                              float* __restrict__ gr,
                              const float* __restrict__ thr_p, const float* __restrict__ ratio_p)
{
    int idx = blockIdx.x * blockDim.x + threadIdx.x;
    if (idx >= NCH * NT) return;
    int c = idx / NT;
    int t = idx - c * NT;
    float v = ola_at(frames, c, t);
    out[idx] = v;
    float thr = thr_p[0];
    float ratio = ratio_p[0];
    float aa = fabsf(v) + 1e-8f;
    float adb = 20.f * __log10f(aa);
    gr[idx] = fmaxf(adb - thr, 0.f) * (1.f - 1.f / ratio);
}

// Warp-cooperative compressor scan v7 (chained chunks + software-pipelined tile body).
// Recurrence (exact, branchless): state' = max(fma(1-a_att,s,a_att*g), fma(1-a_rel,s,a_rel*g))
__global__ void __launch_bounds__(64, 2)
scan_kernel(const float* __restrict__ gr, float* __restrict__ gs,
            const float* __restrict__ att_p, const float* __restrict__ rel_p)
{
    __shared__ float sbuf[2][2][32][33];   // [warp][dblbuf][row=lane-stream][col=step]

    const int w = threadIdx.x >> 5;
    const int lane = threadIdx.x & 31;
    const int warpGlobal = blockIdx.x * 2 + w;
    const int chunkBase = warpGlobal * 64;     // 176 warps/ch cover 11264 >= NC
    const int c = blockIdx.y;

    const float a_att = 1.f - __expf(-1.f / (att_p[0] * 48000.f));
    const float a_rel = 1.f - __expf(-1.f / (rel_p[0] * 48000.f));
    const float m_att = 1.f - a_att, m_rel = 1.f - a_rel;

    const float* grc = gr + c * NT;
    float* gsc = gs + c * NT;

    const int row0 = lane >> 3;          // 0..3
    const int quad = (lane & 7) << 2;    // 0,4,..,28
    const int gbase = chunkBase * CHUNK - WARM;          // stream base of row 0
    const bool clampW = (warpGlobal == 0) || (chunkBase + 64 > NC);

    float state = 0.f;
    float4 nxA[8], nxB[8];

#define STEP(gv) state = fmaxf(fmaf(m_att, state, a_att * (gv)), fmaf(m_rel, state, a_rel * (gv)))

#define LOADT(dd, nx) do {                                                    \
        int _tb = gbase + (dd) * 32 + quad;                                   \
        if (clampW) {                                                         \
            _Pragma("unroll")                                                 \
            for (int i = 0; i < 8; ++i) {                                     \
                int _a = _tb + (row0 + 4 * i) * SPAN;                         \
                _a = max(0, min(_a, NT - 4));                                 \
                nx[i] = *(const float4*)(grc + _a);                           \
            }                                                                 \
        } else {                                                              \
            _Pragma("unroll")                                                 \
            for (int i = 0; i < 8; ++i)                                       \
                nx[i] = *(const float4*)(grc + _tb + (row0 + 4 * i) * SPAN);  \
        }                                                                     \
    } while (0)

#define STORET(bb, nx) do {                                                   \
        _Pragma("unroll")                                                     \
        for (int i = 0; i < 8; ++i) {                                         \
            int _r = row0 + 4 * i;                                            \
            sbuf[w][bb][_r][quad + 0] = nx[i].x;                              \
            sbuf[w][bb][_r][quad + 1] = nx[i].y;                              \
            sbuf[w][bb][_r][quad + 2] = nx[i].z;                              \
            sbuf[w][bb][_r][quad + 3] = nx[i].w;                              \
        }                                                                     \
    } while (0)

#define TILE_BODY(b, bb, nx, DOSTS, DOOUT) do {                               \
        float p[32];                                                          \
        _Pragma("unroll")                                                     \
        for (int j0 = 0; j0 < 8; ++j0) p[j0] = sbuf[w][b][lane][j0];          \
        const int tf0 = gbase + lane * SPAN + d * 32;                         \
        _Pragma("unroll")                                                     \
        for (int j = 0; j < 32; ++j) {                                        \
            if (j < 24) p[j + 8] = sbuf[w][b][lane][j + 8];                   \
            if (DOSTS) {                                                      \
                const int _i = j >> 2, _cpt = j & 3;                          \
                float _v = (_cpt == 0) ? nx[_i].x : (_cpt == 1) ? nx[_i].y    \
                           : (_cpt == 2) ? nx[_i].z : nx[_i].w;               \
                sbuf[w][bb][row0 + 4 * _i][quad + _cpt] = _v;                 \
            }                                                                 \
            if (tf0 + j >= 1) STEP(p[j]);                                     \
            if (DOOUT) sbuf[w][b][lane][j] = state;                           \
        }                                                                     \
    } while (0)

    LOADT(0, nxA);
    STORET(0, nxA);
    LOADT(1, nxB);
    __syncwarp();

    // ---- warm phase (no output) ----
    for (int d = 0; d < WARMT2; ++d) {
        const int b = d & 1, bb = (d + 1) & 1;
        if ((d & 1) == 0) {
            if (d + 2 < NTILES2) LOADT(d + 2, nxA);
            TILE_BODY(b, bb, nxB, true, false);
        } else {
            if (d + 2 < NTILES2) LOADT(d + 2, nxB);
            TILE_BODY(b, bb, nxA, true, false);
        }
        __syncwarp();
    }

    // ---- store phase (last 16 tiles = 512 output samples per lane) ----
    for (int d = WARMT2; d < NTILES2; ++d) {
        const int b = d & 1, bb = (d + 1) & 1;
        const bool hasNext = (d + 1 < NTILES2);
        if ((d & 1) == 0) {
            if (d + 2 < NTILES2) LOADT(d + 2, nxA);
            if (hasNext) TILE_BODY(b, bb, nxB, true, true);
            else         TILE_BODY(b, bb, nxB, false, true);
        } else {
            if (d + 2 < NTILES2) LOADT(d + 2, nxB);
            if (hasNext) TILE_BODY(b, bb, nxA, true, true);
            else         TILE_BODY(b, bb, nxA, false, true);
        }
        __syncwarp();
        const int s = d - WARMT2;
#pragma unroll 8
        for (int r = 0; r < 32; ++r) {
            int tout = (chunkBase + 2 * r) * CHUNK + s * 32 + lane;
            if (tout < NT) gsc[tout] = sbuf[w][b][r][lane];
        }
        __syncwarp();
    }
#undef STEP
#undef LOADT
#undef STORET
#undef TILE_BODY
}

// apply smoothed gain + makeup, then saturation
__global__ void final_kernel(const float* __restrict__ x, const float* __restrict__ gs,
                             float* __restrict__ out,
                             const float* __restrict__ makeup_p, const float* __restrict__ sat_p)
{
    int idx = blockIdx.x * blockDim.x + threadIdx.x;
    if (idx >= NCH * NT) return;
    float mk = makeup_p[0];
    float sat = sat_p[0];
    float xv = x[idx];
    float aa = fabsf(xv) + 1e-8f;
    float gl = __expf((mk - gs[idx]) * 0.05f * LN10_F);
    float sgn = (xv > 0.f) ? 1.f : ((xv < 0.f) ? -1.f : 0.f);
    float y = sgn * aa * gl;
    if (sat > 1.f) {
        float z = y * sat;
        float e = __expf(2.f * z);
        y = ((e - 1.f) / (e + 1.f)) / sat;
    }
    out[idx] = y;
}

extern "C" void kernel_launch(void* const* d_in, const int* in_sizes, int n_in,
                              void* d_out, int out_size)
{
    const float* audio      = (const float*)d_in[0];
    const float* eq_low     = (const float*)d_in[1];
    const float* eq_lowmid  = (const float*)d_in[2];
    const float* eq_highmid = (const float*)d_in[3];
    const float* eq_high    = (const float*)d_in[4];
    const float* thr        = (const float*)d_in[5];
    const float* ratio      = (const float*)d_in[6];
    const float* attack     = (const float*)d_in[7];
    const float* release    = (const float*)d_in[8];
    const float* makeup     = (const float*)d_in[9];
    const float* satur      = (const float*)d_in[10];
    float* out = (float*)d_out;

    float *sigA, *sigB, *frames;
    cudaGetSymbolAddress((void**)&sigA, g_sigA);
    cudaGetSymbolAddress((void**)&sigB, g_sigB);
    cudaGetSymbolAddress((void**)&frames, g_frames);
    float* gs = frames;   // frames buffer reused after final OLA

    dim3 gEq(NPAIRS, NCH);
    const int EW = 256;
    int ewBlocks = (NCH * NT + EW - 1) / EW;

    win_init_kernel<<<(N_FFT + 255) / 256, 256>>>();
    mask_init_kernel<<<(N_FFT + 255) / 256, 256>>>(eq_low, eq_lowmid, eq_highmid, eq_high);

    // EQ band chain (ping-pong)
    eq_pair_kernel<<<gEq, 128>>>(audio, frames, 0);
    ola_kernel<<<ewBlocks, EW>>>(frames, sigA);
    eq_pair_kernel<<<gEq, 128>>>(sigA, frames, 1);
    ola_kernel<<<ewBlocks, EW>>>(frames, sigB);
    eq_pair_kernel<<<gEq, 128>>>(sigB, frames, 2);
    ola_kernel<<<ewBlocks, EW>>>(frames, sigA);
    eq_pair_kernel<<<gEq, 128>>>(sigA, frames, 3);
    // band 4 OLA fused with gain-reduction: audio -> sigB, gr -> sigA
    ola_gr_kernel<<<ewBlocks, EW>>>(frames, sigB, sigA, thr, ratio);

    // pipelined chained-chunk compressor envelope (gs into frames buffer)
    dim3 gScan(88, NCH);
    scan_kernel<<<gScan, 64>>>(sigA, gs, attack, release);

    // gain + saturation
    final_kernel<<<ewBlocks, EW>>>(sigB, gs, out, makeup, satur);
}